// round 8
// baseline (speedup 1.0000x reference)
#include <cuda_runtime.h>
#include <cuda_fp16.h>
#include <cstdint>

// Problem constants (from reference setup_inputs)
#define NMAX 50048
#define EMAX 1600000
#define F 128

// Scratch (allocation-free rule: __device__ globals)
__device__ __align__(16) __half g_p[NMAX * F];    // relu(h @ W_pool + b_pool)
__device__ __align__(16) __half g_agg[NMAX * F];  // segment max
__device__ __align__(16) __half g_h1[NMAX * F];   // layer-1 output
__device__ __align__(16) __half g_x16[NMAX * F];  // fp16 copy of x
__device__ __align__(16) __half g_w[6 * F * F];   // fp16 weights
__device__ __align__(16) float g_tmp[NMAX * F];   // self-GEMM partial (fp32)

// CSR-by-dst scratch
__device__ int g_cnt[NMAX];
__device__ int g_rowptr[NMAX + 1];
__device__ int g_cursor[NMAX];
__device__ int g_eidx[EMAX];
__device__ int g_blksum[64];

// ---------------------------------------------------------------------------
// Helpers
// ---------------------------------------------------------------------------
__device__ __forceinline__ void cp16(void* smem_dst, const void* gsrc) {
    unsigned d = (unsigned)__cvta_generic_to_shared(smem_dst);
    asm volatile("cp.async.cg.shared.global [%0], [%1], 16;" :: "r"(d), "l"(gsrc));
}
#define CP_COMMIT() asm volatile("cp.async.commit_group;")
#define CP_WAIT0()  asm volatile("cp.async.wait_group 0;")

__device__ __forceinline__ void mma_f16(float* d, const unsigned* a, const unsigned* b) {
    asm volatile(
        "mma.sync.aligned.m16n8k16.row.col.f32.f16.f16.f32 "
        "{%0,%1,%2,%3}, {%4,%5,%6,%7}, {%8,%9}, {%0,%1,%2,%3};"
        : "+f"(d[0]), "+f"(d[1]), "+f"(d[2]), "+f"(d[3])
        : "r"(a[0]), "r"(a[1]), "r"(a[2]), "r"(a[3]), "r"(b[0]), "r"(b[1]));
}

__device__ __forceinline__ void ldsm_x4(unsigned* a, unsigned saddr) {
    asm volatile("ldmatrix.sync.aligned.m8n8.x4.shared.b16 {%0,%1,%2,%3}, [%4];"
        : "=r"(a[0]), "=r"(a[1]), "=r"(a[2]), "=r"(a[3]) : "r"(saddr));
}
__device__ __forceinline__ void ldsm_x2_trans(unsigned* b, unsigned saddr) {
    asm volatile("ldmatrix.sync.aligned.m8n8.x2.trans.shared.b16 {%0,%1}, [%2];"
        : "=r"(b[0]), "=r"(b[1]) : "r"(saddr));
}

// ---------------------------------------------------------------------------
// Prep kernels: convert x and the 6 weight matrices to fp16 (once per launch)
// ---------------------------------------------------------------------------
__global__ void conv_x_kernel(const float* __restrict__ in, __half* __restrict__ out, int n8)
{
    int i = blockIdx.x * blockDim.x + threadIdx.x;
    if (i < n8) {
        float4 v0 = ((const float4*)in)[i * 2];
        float4 v1 = ((const float4*)in)[i * 2 + 1];
        __half2 h[4];
        h[0] = __floats2half2_rn(v0.x, v0.y);
        h[1] = __floats2half2_rn(v0.z, v0.w);
        h[2] = __floats2half2_rn(v1.x, v1.y);
        h[3] = __floats2half2_rn(v1.z, v1.w);
        ((float4*)out)[i] = *(float4*)h;
    }
}

__global__ void conv_w_kernel(const float* w0, const float* w1, const float* w2,
                              const float* w3, const float* w4, const float* w5,
                              __half* __restrict__ out)
{
    const float* ws[6] = {w0, w1, w2, w3, w4, w5};
    const float* in = ws[blockIdx.y];
    __half* o = out + blockIdx.y * (F * F);
    int i = blockIdx.x * blockDim.x + threadIdx.x;
    float4 v0 = ((const float4*)in)[i * 2];
    float4 v1 = ((const float4*)in)[i * 2 + 1];
    __half2 h[4];
    h[0] = __floats2half2_rn(v0.x, v0.y);
    h[1] = __floats2half2_rn(v0.z, v0.w);
    h[2] = __floats2half2_rn(v1.x, v1.y);
    h[3] = __floats2half2_rn(v1.z, v1.w);
    ((float4*)o)[i] = *(float4*)h;
}

// ---------------------------------------------------------------------------
// FP16 tensor-core GEMM:  C[M,128] = epi( A @ W (+ Cin) (+ bias) )
// Block: 256 thr = 8 warps (2x4), BM=64, BN=128, BK=64, cp.async dbl-buffered.
// Templates: ADDC (add fp32 Cin), BIAS, L2N (row l2norm), RELU, HALFOUT.
// ---------------------------------------------------------------------------
#define SAH 72
#define SBH 136
#define AS_ELEM (64 * SAH)
#define BS_ELEM (64 * SBH)
#define AS_BYTES (AS_ELEM * 2)
#define BS_BYTES (BS_ELEM * 2)
#define SMEM_BYTES (2 * AS_BYTES + 2 * BS_BYTES)

__device__ __forceinline__ void prefetch_tile(
    __half* As, __half* Bs,
    const __half* A, const __half* W,
    int t, int m0, int M, int tid)
{
    int buf = t & 1;
    int kk = t * 64;
#pragma unroll
    for (int i = 0; i < 2; i++) {
        int c  = tid + i * 256;
        int r  = c >> 3;
        int c8 = (c & 7) * 8;
        int m  = m0 + r;
        if (m < M)
            cp16(&As[buf * AS_ELEM + r * SAH + c8], A + (size_t)m * F + kk + c8);
    }
#pragma unroll
    for (int i = 0; i < 4; i++) {
        int c  = tid + i * 256;
        int r  = c >> 4;
        int n8 = (c & 15) * 8;
        cp16(&Bs[buf * BS_ELEM + r * SBH + n8], W + (size_t)(kk + r) * F + n8);
    }
    CP_COMMIT();
}

template<bool ADDC, bool BIAS, bool L2N, bool RELU, bool HALFOUT>
__global__ __launch_bounds__(256, 3)
void gemm_tc_kernel(const __half* __restrict__ A, const __half* __restrict__ W,
                    const float* __restrict__ Cin,
                    const float* __restrict__ bias, void* __restrict__ Cout, int M)
{
    extern __shared__ __align__(16) char smc[];
    __half* As = (__half*)smc;
    __half* Bs = (__half*)(smc + 2 * AS_BYTES);

    const int tid  = threadIdx.x;
    const int wid  = tid >> 5;
    const int lane = tid & 31;
    const int wr   = wid >> 2;
    const int wc   = wid & 3;
    const int g    = lane >> 2;
    const int tig  = lane & 3;
    const int m0   = blockIdx.x * 64;

    unsigned as_u32 = (unsigned)__cvta_generic_to_shared(As);
    unsigned bs_u32 = (unsigned)__cvta_generic_to_shared(Bs);
    const int lrow = lane & 15;
    const int kadd = (lane & 16) ? 8 : 0;
    unsigned aaddr[2];
#pragma unroll
    for (int mf = 0; mf < 2; mf++)
        aaddr[mf] = as_u32 + ((wr * 32 + mf * 16 + lrow) * SAH + kadd) * 2;
    unsigned baddr[4];
#pragma unroll
    for (int nf = 0; nf < 4; nf++)
        baddr[nf] = bs_u32 + (lrow * SBH + (wc * 32 + nf * 8)) * 2;

    float acc[2][4][4];
#pragma unroll
    for (int mf = 0; mf < 2; mf++)
#pragma unroll
        for (int nf = 0; nf < 4; nf++)
#pragma unroll
            for (int q = 0; q < 4; q++) acc[mf][nf][q] = 0.0f;

    prefetch_tile(As, Bs, A, W, 0, m0, M, tid);

#pragma unroll
    for (int t = 0; t < 2; t++) {
        CP_WAIT0();
        __syncthreads();
        if (t + 1 < 2)
            prefetch_tile(As, Bs, A, W, t + 1, m0, M, tid);

        const unsigned abase = (t & 1) * AS_BYTES;
        const unsigned bbase = (t & 1) * BS_BYTES;

#pragma unroll
        for (int s = 0; s < 4; s++) {
            unsigned a[2][4], b[4][2];
#pragma unroll
            for (int mf = 0; mf < 2; mf++)
                ldsm_x4(a[mf], aaddr[mf] + abase + s * 32);
#pragma unroll
            for (int nf = 0; nf < 4; nf++)
                ldsm_x2_trans(b[nf], baddr[nf] + bbase + s * (16 * SBH * 2));
#pragma unroll
            for (int mf = 0; mf < 2; mf++)
#pragma unroll
                for (int nf = 0; nf < 4; nf++)
                    mma_f16(acc[mf][nf], a[mf], b[nf]);
        }
    }

    // ---- epilogue ----
    if (BIAS) {
        float bv0[4], bv1[4];
#pragma unroll
        for (int nf = 0; nf < 4; nf++) {
            int cb = wc * 32 + nf * 8 + 2 * tig;
            bv0[nf] = bias[cb];
            bv1[nf] = bias[cb + 1];
        }
#pragma unroll
        for (int mf = 0; mf < 2; mf++)
#pragma unroll
            for (int nf = 0; nf < 4; nf++) {
                acc[mf][nf][0] += bv0[nf];
                acc[mf][nf][1] += bv1[nf];
                acc[mf][nf][2] += bv0[nf];
                acc[mf][nf][3] += bv1[nf];
            }
    }

    if (ADDC) {
#pragma unroll
        for (int mf = 0; mf < 2; mf++)
#pragma unroll
            for (int half = 0; half < 2; half++) {
                int m = m0 + wr * 32 + mf * 16 + half * 8 + g;
                if (m >= M) continue;
#pragma unroll
                for (int nf = 0; nf < 4; nf++) {
                    int col = wc * 32 + nf * 8 + 2 * tig;
                    float2 c = *(const float2*)(Cin + (size_t)m * F + col);
                    acc[mf][nf][half * 2 + 0] += c.x;
                    acc[mf][nf][half * 2 + 1] += c.y;
                }
            }
    }

    float inv[2][2];
#pragma unroll
    for (int mf = 0; mf < 2; mf++) { inv[mf][0] = 1.f; inv[mf][1] = 1.f; }

    if (L2N) {
        __syncthreads();
        float* rowsq = (float*)smc;
        if (tid < 64) rowsq[tid] = 0.0f;
        __syncthreads();
#pragma unroll
        for (int mf = 0; mf < 2; mf++) {
#pragma unroll
            for (int half = 0; half < 2; half++) {
                float s = 0.f;
#pragma unroll
                for (int nf = 0; nf < 4; nf++) {
                    float v0 = acc[mf][nf][half * 2 + 0];
                    float v1 = acc[mf][nf][half * 2 + 1];
                    s = fmaf(v0, v0, fmaf(v1, v1, s));
                }
                s += __shfl_xor_sync(0xffffffffu, s, 1);
                s += __shfl_xor_sync(0xffffffffu, s, 2);
                if (tig == 0) {
                    int r = wr * 32 + mf * 16 + half * 8 + g;
                    atomicAdd(&rowsq[r], s);
                }
            }
        }
        __syncthreads();
#pragma unroll
        for (int mf = 0; mf < 2; mf++)
#pragma unroll
            for (int half = 0; half < 2; half++) {
                int r = wr * 32 + mf * 16 + half * 8 + g;
                inv[mf][half] = 1.0f / fmaxf(sqrtf(rowsq[r]), 1e-12f);
            }
    }

#pragma unroll
    for (int mf = 0; mf < 2; mf++) {
#pragma unroll
        for (int half = 0; half < 2; half++) {
            int m = m0 + wr * 32 + mf * 16 + half * 8 + g;
            if (m >= M) continue;
            float s = inv[mf][half];
#pragma unroll
            for (int nf = 0; nf < 4; nf++) {
                float v0 = acc[mf][nf][half * 2 + 0] * s;
                float v1 = acc[mf][nf][half * 2 + 1] * s;
                if (RELU) { v0 = fmaxf(v0, 0.f); v1 = fmaxf(v1, 0.f); }
                int col = wc * 32 + nf * 8 + 2 * tig;
                if (HALFOUT) {
                    __half2 hv = __floats2half2_rn(v0, v1);
                    *(__half2*)((__half*)Cout + (size_t)m * F + col) = hv;
                } else {
                    *(float2*)((float*)Cout + (size_t)m * F + col) = make_float2(v0, v1);
                }
            }
        }
    }
}

// ---------------------------------------------------------------------------
// CSR-by-dst build
// ---------------------------------------------------------------------------
__global__ void hist_kernel(const int* __restrict__ dst, int* __restrict__ cnt, int E)
{
    int e = blockIdx.x * blockDim.x + threadIdx.x;
    if (e < E) atomicAdd(&cnt[dst[e]], 1);
}

#define SCAN_CHUNK 1024
__global__ void scan_block_kernel(const int* __restrict__ cnt, int* __restrict__ rowptr,
                                  int* __restrict__ blksum, int N)
{
    __shared__ int s[SCAN_CHUNK];
    int i = blockIdx.x * SCAN_CHUNK + threadIdx.x;
    int v = (i < N) ? cnt[i] : 0;
    s[threadIdx.x] = v;
    __syncthreads();
#pragma unroll
    for (int off = 1; off < SCAN_CHUNK; off <<= 1) {
        int t = (threadIdx.x >= off) ? s[threadIdx.x - off] : 0;
        __syncthreads();
        s[threadIdx.x] += t;
        __syncthreads();
    }
    if (i < N) rowptr[i] = s[threadIdx.x] - v;
    if (threadIdx.x == SCAN_CHUNK - 1) blksum[blockIdx.x] = s[threadIdx.x];
}

__global__ void scan_partials_kernel(int* blksum, int nb)
{
    int lane = threadIdx.x & 31;
    int v0 = (lane < nb) ? blksum[lane] : 0;
    int v1 = (lane + 32 < nb) ? blksum[lane + 32] : 0;
    int s0 = v0, s1 = v1;
#pragma unroll
    for (int o = 1; o < 32; o <<= 1) {
        int t0 = __shfl_up_sync(0xffffffffu, s0, o);
        int t1 = __shfl_up_sync(0xffffffffu, s1, o);
        if (lane >= o) { s0 += t0; s1 += t1; }
    }
    int tot0 = __shfl_sync(0xffffffffu, s0, 31);
    s1 += tot0;
    if (lane < nb) blksum[lane] = s0 - v0;
    if (lane + 32 < nb) blksum[lane + 32] = s1 - v1;
}

__global__ void add_offsets_kernel(int* __restrict__ rowptr, int* __restrict__ cursor,
                                   const int* __restrict__ blksum, int N, int E)
{
    int i = blockIdx.x * blockDim.x + threadIdx.x;
    if (i < N) {
        int v = rowptr[i] + blksum[i >> 10];
        rowptr[i] = v;
        cursor[i] = v;
    }
    if (i == N) rowptr[N] = E;
}

__global__ void fill_csr_kernel(const int* __restrict__ src, const int* __restrict__ dst,
                                int* __restrict__ cursor, int* __restrict__ eidx, int E)
{
    int e = blockIdx.x * blockDim.x + threadIdx.x;
    if (e < E) {
        int pos = atomicAdd(&cursor[dst[e]], 1);
        eidx[pos] = src[e];
    }
}

// ---------------------------------------------------------------------------
// Gather-max over fp16 rows: one warp per dst node, lane owns 4 halfs (8B)
// ---------------------------------------------------------------------------
__global__ void gather_max_kernel(const __half2* __restrict__ p2,
                                  const int* __restrict__ rowptr,
                                  const int* __restrict__ eidx,
                                  __half2* __restrict__ agg, int N)
{
    int warp = (blockIdx.x * blockDim.x + threadIdx.x) >> 5;
    int lane = threadIdx.x & 31;
    if (warp >= N) return;
    int beg = __ldg(&rowptr[warp]);
    int end = __ldg(&rowptr[warp + 1]);

    __half2 z = __float2half2_rn(0.f);
    __half2 a0 = z, a1 = z;
    int i = beg;
    for (; i + 3 < end; i += 4) {
        int s0 = __ldg(&eidx[i]);
        int s1 = __ldg(&eidx[i + 1]);
        int s2 = __ldg(&eidx[i + 2]);
        int s3 = __ldg(&eidx[i + 3]);
        const __half2* r0 = p2 + (size_t)s0 * 64 + lane * 2;
        const __half2* r1 = p2 + (size_t)s1 * 64 + lane * 2;
        const __half2* r2 = p2 + (size_t)s2 * 64 + lane * 2;
        const __half2* r3 = p2 + (size_t)s3 * 64 + lane * 2;
        __half2 v00 = r0[0], v01 = r0[1];
        __half2 v10 = r1[0], v11 = r1[1];
        __half2 v20 = r2[0], v21 = r2[1];
        __half2 v30 = r3[0], v31 = r3[1];
        a0 = __hmax2(a0, __hmax2(__hmax2(v00, v10), __hmax2(v20, v30)));
        a1 = __hmax2(a1, __hmax2(__hmax2(v01, v11), __hmax2(v21, v31)));
    }
    for (; i < end; i++) {
        int s = __ldg(&eidx[i]);
        const __half2* r = p2 + (size_t)s * 64 + lane * 2;
        a0 = __hmax2(a0, r[0]);
        a1 = __hmax2(a1, r[1]);
    }
    __half2 o[2] = {a0, a1};
    *(float2*)(agg + (size_t)warp * 64 + lane * 2) = *(float2*)o;
}

// ---------------------------------------------------------------------------
extern "C" void kernel_launch(void* const* d_in, const int* in_sizes, int n_in,
                              void* d_out, int out_size)
{
    const float* x       = (const float*)d_in[0];
    const int*   src     = (const int*)  d_in[1];
    const int*   dst     = (const int*)  d_in[2];
    const float* W_pool1 = (const float*)d_in[3];
    const float* b_pool1 = (const float*)d_in[4];
    const float* W_self1 = (const float*)d_in[5];
    const float* W_neigh1= (const float*)d_in[6];
    const float* b1      = (const float*)d_in[7];
    const float* W_pool2 = (const float*)d_in[8];
    const float* b_pool2 = (const float*)d_in[9];
    const float* W_self2 = (const float*)d_in[10];
    const float* W_neigh2= (const float*)d_in[11];
    const float* b2      = (const float*)d_in[12];

    const int M = in_sizes[0] / F;       // 50000
    const int E = in_sizes[1];           // 1600000

    __half *p, *agg, *h1, *x16, *w;
    float* tmp;
    int *cnt, *rowptr, *cursor, *eidx, *blksum;
    cudaGetSymbolAddress((void**)&p,      g_p);
    cudaGetSymbolAddress((void**)&agg,    g_agg);
    cudaGetSymbolAddress((void**)&h1,     g_h1);
    cudaGetSymbolAddress((void**)&x16,    g_x16);
    cudaGetSymbolAddress((void**)&w,      g_w);
    cudaGetSymbolAddress((void**)&tmp,    g_tmp);
    cudaGetSymbolAddress((void**)&cnt,    g_cnt);
    cudaGetSymbolAddress((void**)&rowptr, g_rowptr);
    cudaGetSymbolAddress((void**)&cursor, g_cursor);
    cudaGetSymbolAddress((void**)&eidx,   g_eidx);
    cudaGetSymbolAddress((void**)&blksum, g_blksum);
    float* out = (float*)d_out;

    const __half* rWp1 = w + 0 * F * F;
    const __half* rWs1 = w + 1 * F * F;
    const __half* rWn1 = w + 2 * F * F;
    const __half* rWp2 = w + 3 * F * F;
    const __half* rWs2 = w + 4 * F * F;
    const __half* rWn2 = w + 5 * F * F;

    // gemm variants: pool / self / neigh1 / neigh2
    auto k_pool  = gemm_tc_kernel<false, true,  false, true,  true >;
    auto k_self  = gemm_tc_kernel<false, true,  false, false, false>;
    auto k_ngh1  = gemm_tc_kernel<true,  false, true,  true,  true >;
    auto k_ngh2  = gemm_tc_kernel<true,  false, true,  true,  false>;
    cudaFuncSetAttribute(k_pool, cudaFuncAttributeMaxDynamicSharedMemorySize, SMEM_BYTES);
    cudaFuncSetAttribute(k_self, cudaFuncAttributeMaxDynamicSharedMemorySize, SMEM_BYTES);
    cudaFuncSetAttribute(k_ngh1, cudaFuncAttributeMaxDynamicSharedMemorySize, SMEM_BYTES);
    cudaFuncSetAttribute(k_ngh2, cudaFuncAttributeMaxDynamicSharedMemorySize, SMEM_BYTES);

    const int gblocks = (M + 63) / 64;
    const int eblocks = (E + 255) / 256;
    const int nb      = (M + SCAN_CHUNK - 1) / SCAN_CHUNK;
    const int wblocks = (M * 32 + 255) / 256;

    // --- side streams + events (host objects only; created once) ---
    static cudaStream_t s_csr = nullptr, s_self = nullptr;
    static cudaEvent_t ev_fork = nullptr, ev_csr = nullptr, ev_conv = nullptr,
                       ev_tmp1 = nullptr, ev_h1 = nullptr, ev_tmp2 = nullptr;
    if (s_csr == nullptr) {
        cudaStreamCreateWithFlags(&s_csr, cudaStreamNonBlocking);
        cudaStreamCreateWithFlags(&s_self, cudaStreamNonBlocking);
        cudaEventCreateWithFlags(&ev_fork, cudaEventDisableTiming);
        cudaEventCreateWithFlags(&ev_csr, cudaEventDisableTiming);
        cudaEventCreateWithFlags(&ev_conv, cudaEventDisableTiming);
        cudaEventCreateWithFlags(&ev_tmp1, cudaEventDisableTiming);
        cudaEventCreateWithFlags(&ev_h1, cudaEventDisableTiming);
        cudaEventCreateWithFlags(&ev_tmp2, cudaEventDisableTiming);
    }

    // Fork CSR branch
    cudaEventRecord(ev_fork, 0);
    cudaStreamWaitEvent(s_csr, ev_fork, 0);
    cudaMemsetAsync(cnt, 0, (size_t)M * sizeof(int), s_csr);
    hist_kernel<<<eblocks, 256, 0, s_csr>>>(dst, cnt, E);
    scan_block_kernel<<<nb, SCAN_CHUNK, 0, s_csr>>>(cnt, rowptr, blksum, M);
    scan_partials_kernel<<<1, 32, 0, s_csr>>>(blksum, nb);
    add_offsets_kernel<<<(M + 256) / 256, 256, 0, s_csr>>>(rowptr, cursor, blksum, M, E);
    fill_csr_kernel<<<eblocks, 256, 0, s_csr>>>(src, dst, cursor, eidx, E);
    cudaEventRecord(ev_csr, s_csr);

    // Main: convert inputs
    conv_w_kernel<<<dim3(8, 6), 256>>>(W_pool1, W_self1, W_neigh1,
                                       W_pool2, W_self2, W_neigh2, w);
    conv_x_kernel<<<(M * F / 8 + 255) / 256, 256>>>(x, x16, M * F / 8);
    cudaEventRecord(ev_conv, 0);

    // self1 on its own stream (overlaps pool GEMM + gather1)
    cudaStreamWaitEvent(s_self, ev_conv, 0);
    k_self<<<gblocks, 256, SMEM_BYTES, s_self>>>(x16, rWs1, nullptr, b1, tmp, M);
    cudaEventRecord(ev_tmp1, s_self);

    // ---- Layer 1 main chain ----
    k_pool<<<gblocks, 256, SMEM_BYTES>>>(x16, rWp1, nullptr, b_pool1, p, M);
    cudaStreamWaitEvent(0, ev_csr, 0);
    gather_max_kernel<<<wblocks, 256>>>((const __half2*)p, rowptr, eidx, (__half2*)agg, M);
    cudaStreamWaitEvent(0, ev_tmp1, 0);
    k_ngh1<<<gblocks, 256, SMEM_BYTES>>>(agg, rWn1, tmp, nullptr, h1, M);
    cudaEventRecord(ev_h1, 0);

    // self2 overlaps pool2 + gather2
    cudaStreamWaitEvent(s_self, ev_h1, 0);
    k_self<<<gblocks, 256, SMEM_BYTES, s_self>>>(h1, rWs2, nullptr, b2, tmp, M);
    cudaEventRecord(ev_tmp2, s_self);

    // ---- Layer 2 main chain ----
    k_pool<<<gblocks, 256, SMEM_BYTES>>>(h1, rWp2, nullptr, b_pool2, p, M);
    gather_max_kernel<<<wblocks, 256>>>((const __half2*)p, rowptr, eidx, (__half2*)agg, M);
    cudaStreamWaitEvent(0, ev_tmp2, 0);
    k_ngh2<<<gblocks, 256, SMEM_BYTES>>>(agg, rWn2, tmp, nullptr, out, M);
}

// round 9
// speedup vs baseline: 1.0083x; 1.0083x over previous
#include <cuda_runtime.h>
#include <cuda_fp16.h>
#include <cstdint>

// Problem constants (from reference setup_inputs)
#define NMAX 50048
#define EMAX 1600000
#define F 128

// Scratch (allocation-free rule: __device__ globals)
__device__ __align__(16) __half g_p[NMAX * F];    // relu(h @ W_pool + b_pool)
__device__ __align__(16) __half g_agg[NMAX * F];  // segment max
__device__ __align__(16) __half g_h1[NMAX * F];   // layer-1 output
__device__ __align__(16) __half g_x16[NMAX * F];  // fp16 copy of x
__device__ __align__(16) __half g_w[6 * F * F];   // fp16 weights

// CSR-by-dst scratch
__device__ int g_cnt[NMAX];
__device__ int g_rowptr[NMAX + 1];
__device__ int g_cursor[NMAX];
__device__ int g_eidx[EMAX];
__device__ int g_blksum[64];

// ---------------------------------------------------------------------------
// Helpers
// ---------------------------------------------------------------------------
__device__ __forceinline__ void cp16(void* smem_dst, const void* gsrc) {
    unsigned d = (unsigned)__cvta_generic_to_shared(smem_dst);
    asm volatile("cp.async.cg.shared.global [%0], [%1], 16;" :: "r"(d), "l"(gsrc));
}
#define CP_COMMIT() asm volatile("cp.async.commit_group;")
#define CP_WAIT0()  asm volatile("cp.async.wait_group 0;")

__device__ __forceinline__ void mma_f16(float* d, const unsigned* a, const unsigned* b) {
    asm volatile(
        "mma.sync.aligned.m16n8k16.row.col.f32.f16.f16.f32 "
        "{%0,%1,%2,%3}, {%4,%5,%6,%7}, {%8,%9}, {%0,%1,%2,%3};"
        : "+f"(d[0]), "+f"(d[1]), "+f"(d[2]), "+f"(d[3])
        : "r"(a[0]), "r"(a[1]), "r"(a[2]), "r"(a[3]), "r"(b[0]), "r"(b[1]));
}

__device__ __forceinline__ void ldsm_x4(unsigned* a, unsigned saddr) {
    asm volatile("ldmatrix.sync.aligned.m8n8.x4.shared.b16 {%0,%1,%2,%3}, [%4];"
        : "=r"(a[0]), "=r"(a[1]), "=r"(a[2]), "=r"(a[3]) : "r"(saddr));
}
__device__ __forceinline__ void ldsm_x2_trans(unsigned* b, unsigned saddr) {
    asm volatile("ldmatrix.sync.aligned.m8n8.x2.trans.shared.b16 {%0,%1}, [%2];"
        : "=r"(b[0]), "=r"(b[1]) : "r"(saddr));
}

// ---------------------------------------------------------------------------
// Prep kernels: convert x and the 6 weight matrices to fp16 (once per launch)
// ---------------------------------------------------------------------------
__global__ void conv_x_kernel(const float* __restrict__ in, __half* __restrict__ out, int n8)
{
    int i = blockIdx.x * blockDim.x + threadIdx.x;
    if (i < n8) {
        float4 v0 = ((const float4*)in)[i * 2];
        float4 v1 = ((const float4*)in)[i * 2 + 1];
        __half2 h[4];
        h[0] = __floats2half2_rn(v0.x, v0.y);
        h[1] = __floats2half2_rn(v0.z, v0.w);
        h[2] = __floats2half2_rn(v1.x, v1.y);
        h[3] = __floats2half2_rn(v1.z, v1.w);
        ((float4*)out)[i] = *(float4*)h;
    }
}

__global__ void conv_w_kernel(const float* w0, const float* w1, const float* w2,
                              const float* w3, const float* w4, const float* w5,
                              __half* __restrict__ out)
{
    const float* ws[6] = {w0, w1, w2, w3, w4, w5};
    const float* in = ws[blockIdx.y];
    __half* o = out + blockIdx.y * (F * F);
    int i = blockIdx.x * blockDim.x + threadIdx.x;
    float4 v0 = ((const float4*)in)[i * 2];
    float4 v1 = ((const float4*)in)[i * 2 + 1];
    __half2 h[4];
    h[0] = __floats2half2_rn(v0.x, v0.y);
    h[1] = __floats2half2_rn(v0.z, v0.w);
    h[2] = __floats2half2_rn(v1.x, v1.y);
    h[3] = __floats2half2_rn(v1.z, v1.w);
    ((float4*)o)[i] = *(float4*)h;
}

// ---------------------------------------------------------------------------
// FP16 tensor-core GEMM:  C[M,128] = epi( A1 @ W1 (+ A2 @ W2) + bias )
// Block: 256 thr = 8 warps (2x4), BM=64, BN=128, BK=64, cp.async dbl-buffered.
// Row-local: callers may pass pointer-offset row chunks.
// ---------------------------------------------------------------------------
#define SAH 72
#define SBH 136
#define AS_ELEM (64 * SAH)
#define BS_ELEM (64 * SBH)
#define AS_BYTES (AS_ELEM * 2)
#define BS_BYTES (BS_ELEM * 2)
#define SMEM_BYTES (2 * AS_BYTES + 2 * BS_BYTES)

template<bool TWO>
__device__ __forceinline__ void prefetch_tile(
    __half* As, __half* Bs,
    const __half* A1, const __half* W1, const __half* A2, const __half* W2,
    int t, int m0, int M, int tid)
{
    int buf = t & 1;
    const __half* A = (TWO && t >= 2) ? A2 : A1;
    const __half* W = (TWO && t >= 2) ? W2 : W1;
    int kk = (t & 1) * 64;
#pragma unroll
    for (int i = 0; i < 2; i++) {
        int c  = tid + i * 256;
        int r  = c >> 3;
        int c8 = (c & 7) * 8;
        int m  = m0 + r;
        if (m < M)
            cp16(&As[buf * AS_ELEM + r * SAH + c8], A + (size_t)m * F + kk + c8);
    }
#pragma unroll
    for (int i = 0; i < 4; i++) {
        int c  = tid + i * 256;
        int r  = c >> 4;
        int n8 = (c & 15) * 8;
        cp16(&Bs[buf * BS_ELEM + r * SBH + n8], W + (size_t)(kk + r) * F + n8);
    }
    CP_COMMIT();
}

template<bool TWO, bool L2N, bool HALFOUT>
__global__ __launch_bounds__(256, 3)
void gemm_tc_kernel(const __half* __restrict__ A1, const __half* __restrict__ W1,
                    const __half* __restrict__ A2, const __half* __restrict__ W2,
                    const float* __restrict__ bias, void* __restrict__ Cout, int M)
{
    extern __shared__ __align__(16) char smc[];
    __half* As = (__half*)smc;
    __half* Bs = (__half*)(smc + 2 * AS_BYTES);

    const int tid  = threadIdx.x;
    const int wid  = tid >> 5;
    const int lane = tid & 31;
    const int wr   = wid >> 2;
    const int wc   = wid & 3;
    const int g    = lane >> 2;
    const int tig  = lane & 3;
    const int m0   = blockIdx.x * 64;

    unsigned as_u32 = (unsigned)__cvta_generic_to_shared(As);
    unsigned bs_u32 = (unsigned)__cvta_generic_to_shared(Bs);
    const int lrow = lane & 15;
    const int kadd = (lane & 16) ? 8 : 0;
    unsigned aaddr[2];
#pragma unroll
    for (int mf = 0; mf < 2; mf++)
        aaddr[mf] = as_u32 + ((wr * 32 + mf * 16 + lrow) * SAH + kadd) * 2;
    unsigned baddr[4];
#pragma unroll
    for (int nf = 0; nf < 4; nf++)
        baddr[nf] = bs_u32 + (lrow * SBH + (wc * 32 + nf * 8)) * 2;

    float acc[2][4][4];
#pragma unroll
    for (int mf = 0; mf < 2; mf++)
#pragma unroll
        for (int nf = 0; nf < 4; nf++)
#pragma unroll
            for (int q = 0; q < 4; q++) acc[mf][nf][q] = 0.0f;

    const int T = TWO ? 4 : 2;
    prefetch_tile<TWO>(As, Bs, A1, W1, A2, W2, 0, m0, M, tid);

    for (int t = 0; t < T; t++) {
        CP_WAIT0();
        __syncthreads();
        if (t + 1 < T)
            prefetch_tile<TWO>(As, Bs, A1, W1, A2, W2, t + 1, m0, M, tid);

        const unsigned abase = (t & 1) * AS_BYTES;
        const unsigned bbase = (t & 1) * BS_BYTES;

#pragma unroll
        for (int s = 0; s < 4; s++) {
            unsigned a[2][4], b[4][2];
#pragma unroll
            for (int mf = 0; mf < 2; mf++)
                ldsm_x4(a[mf], aaddr[mf] + abase + s * 32);
#pragma unroll
            for (int nf = 0; nf < 4; nf++)
                ldsm_x2_trans(b[nf], baddr[nf] + bbase + s * (16 * SBH * 2));
#pragma unroll
            for (int mf = 0; mf < 2; mf++)
#pragma unroll
                for (int nf = 0; nf < 4; nf++)
                    mma_f16(acc[mf][nf], a[mf], b[nf]);
        }
    }

    // ---- epilogue ----
    float bv0[4], bv1[4];
#pragma unroll
    for (int nf = 0; nf < 4; nf++) {
        int cb = wc * 32 + nf * 8 + 2 * tig;
        bv0[nf] = bias[cb];
        bv1[nf] = bias[cb + 1];
    }
#pragma unroll
    for (int mf = 0; mf < 2; mf++)
#pragma unroll
        for (int nf = 0; nf < 4; nf++) {
            acc[mf][nf][0] += bv0[nf];
            acc[mf][nf][1] += bv1[nf];
            acc[mf][nf][2] += bv0[nf];
            acc[mf][nf][3] += bv1[nf];
        }

    float inv[2][2];
#pragma unroll
    for (int mf = 0; mf < 2; mf++) { inv[mf][0] = 1.f; inv[mf][1] = 1.f; }

    if (L2N) {
        __syncthreads();
        float* rowsq = (float*)smc;
        if (tid < 64) rowsq[tid] = 0.0f;
        __syncthreads();
#pragma unroll
        for (int mf = 0; mf < 2; mf++) {
#pragma unroll
            for (int half = 0; half < 2; half++) {
                float s = 0.f;
#pragma unroll
                for (int nf = 0; nf < 4; nf++) {
                    float v0 = acc[mf][nf][half * 2 + 0];
                    float v1 = acc[mf][nf][half * 2 + 1];
                    s = fmaf(v0, v0, fmaf(v1, v1, s));
                }
                s += __shfl_xor_sync(0xffffffffu, s, 1);
                s += __shfl_xor_sync(0xffffffffu, s, 2);
                if (tig == 0) {
                    int r = wr * 32 + mf * 16 + half * 8 + g;
                    atomicAdd(&rowsq[r], s);
                }
            }
        }
        __syncthreads();
#pragma unroll
        for (int mf = 0; mf < 2; mf++)
#pragma unroll
            for (int half = 0; half < 2; half++) {
                int r = wr * 32 + mf * 16 + half * 8 + g;
                inv[mf][half] = 1.0f / fmaxf(sqrtf(rowsq[r]), 1e-12f);
            }
    }

#pragma unroll
    for (int mf = 0; mf < 2; mf++) {
#pragma unroll
        for (int half = 0; half < 2; half++) {
            int m = m0 + wr * 32 + mf * 16 + half * 8 + g;
            if (m >= M) continue;
            float s = inv[mf][half];
#pragma unroll
            for (int nf = 0; nf < 4; nf++) {
                float v0 = fmaxf(acc[mf][nf][half * 2 + 0] * s, 0.f);
                float v1 = fmaxf(acc[mf][nf][half * 2 + 1] * s, 0.f);
                int col = wc * 32 + nf * 8 + 2 * tig;
                if (HALFOUT) {
                    __half2 hv = __floats2half2_rn(v0, v1);
                    *(__half2*)((__half*)Cout + (size_t)m * F + col) = hv;
                } else {
                    *(float2*)((float*)Cout + (size_t)m * F + col) = make_float2(v0, v1);
                }
            }
        }
    }
}

// ---------------------------------------------------------------------------
// CSR-by-dst build
// ---------------------------------------------------------------------------
__global__ void hist_kernel(const int* __restrict__ dst, int* __restrict__ cnt, int E)
{
    int e = blockIdx.x * blockDim.x + threadIdx.x;
    if (e < E) atomicAdd(&cnt[dst[e]], 1);
}

#define SCAN_CHUNK 1024
__global__ void scan_block_kernel(const int* __restrict__ cnt, int* __restrict__ rowptr,
                                  int* __restrict__ blksum, int N)
{
    __shared__ int s[SCAN_CHUNK];
    int i = blockIdx.x * SCAN_CHUNK + threadIdx.x;
    int v = (i < N) ? cnt[i] : 0;
    s[threadIdx.x] = v;
    __syncthreads();
#pragma unroll
    for (int off = 1; off < SCAN_CHUNK; off <<= 1) {
        int t = (threadIdx.x >= off) ? s[threadIdx.x - off] : 0;
        __syncthreads();
        s[threadIdx.x] += t;
        __syncthreads();
    }
    if (i < N) rowptr[i] = s[threadIdx.x] - v;
    if (threadIdx.x == SCAN_CHUNK - 1) blksum[blockIdx.x] = s[threadIdx.x];
}

__global__ void scan_partials_kernel(int* blksum, int nb)
{
    int lane = threadIdx.x & 31;
    int v0 = (lane < nb) ? blksum[lane] : 0;
    int v1 = (lane + 32 < nb) ? blksum[lane + 32] : 0;
    int s0 = v0, s1 = v1;
#pragma unroll
    for (int o = 1; o < 32; o <<= 1) {
        int t0 = __shfl_up_sync(0xffffffffu, s0, o);
        int t1 = __shfl_up_sync(0xffffffffu, s1, o);
        if (lane >= o) { s0 += t0; s1 += t1; }
    }
    int tot0 = __shfl_sync(0xffffffffu, s0, 31);
    s1 += tot0;
    if (lane < nb) blksum[lane] = s0 - v0;
    if (lane + 32 < nb) blksum[lane + 32] = s1 - v1;
}

__global__ void add_offsets_kernel(int* __restrict__ rowptr, int* __restrict__ cursor,
                                   const int* __restrict__ blksum, int N, int E)
{
    int i = blockIdx.x * blockDim.x + threadIdx.x;
    if (i < N) {
        int v = rowptr[i] + blksum[i >> 10];
        rowptr[i] = v;
        cursor[i] = v;
    }
    if (i == N) rowptr[N] = E;
}

__global__ void fill_csr_kernel(const int* __restrict__ src, const int* __restrict__ dst,
                                int* __restrict__ cursor, int* __restrict__ eidx, int E)
{
    int e = blockIdx.x * blockDim.x + threadIdx.x;
    if (e < E) {
        int pos = atomicAdd(&cursor[dst[e]], 1);
        eidx[pos] = src[e];
    }
}

// ---------------------------------------------------------------------------
// Gather-max over fp16 rows for dst nodes [nbeg, nend): one warp per node.
// ---------------------------------------------------------------------------
__global__ void gather_max_kernel(const __half2* __restrict__ p2,
                                  const int* __restrict__ rowptr,
                                  const int* __restrict__ eidx,
                                  __half2* __restrict__ agg, int nbeg, int nend)
{
    int warp = nbeg + ((blockIdx.x * blockDim.x + threadIdx.x) >> 5);
    int lane = threadIdx.x & 31;
    if (warp >= nend) return;
    int beg = __ldg(&rowptr[warp]);
    int end = __ldg(&rowptr[warp + 1]);

    __half2 z = __float2half2_rn(0.f);
    __half2 a0 = z, a1 = z;
    int i = beg;
    for (; i + 3 < end; i += 4) {
        int s0 = __ldg(&eidx[i]);
        int s1 = __ldg(&eidx[i + 1]);
        int s2 = __ldg(&eidx[i + 2]);
        int s3 = __ldg(&eidx[i + 3]);
        const __half2* r0 = p2 + (size_t)s0 * 64 + lane * 2;
        const __half2* r1 = p2 + (size_t)s1 * 64 + lane * 2;
        const __half2* r2 = p2 + (size_t)s2 * 64 + lane * 2;
        const __half2* r3 = p2 + (size_t)s3 * 64 + lane * 2;
        __half2 v00 = r0[0], v01 = r0[1];
        __half2 v10 = r1[0], v11 = r1[1];
        __half2 v20 = r2[0], v21 = r2[1];
        __half2 v30 = r3[0], v31 = r3[1];
        a0 = __hmax2(a0, __hmax2(__hmax2(v00, v10), __hmax2(v20, v30)));
        a1 = __hmax2(a1, __hmax2(__hmax2(v01, v11), __hmax2(v21, v31)));
    }
    for (; i < end; i++) {
        int s = __ldg(&eidx[i]);
        const __half2* r = p2 + (size_t)s * 64 + lane * 2;
        a0 = __hmax2(a0, r[0]);
        a1 = __hmax2(a1, r[1]);
    }
    __half2 o[2] = {a0, a1};
    *(float2*)(agg + (size_t)warp * 64 + lane * 2) = *(float2*)o;
}

// ---------------------------------------------------------------------------
extern "C" void kernel_launch(void* const* d_in, const int* in_sizes, int n_in,
                              void* d_out, int out_size)
{
    const float* x       = (const float*)d_in[0];
    const int*   src     = (const int*)  d_in[1];
    const int*   dst     = (const int*)  d_in[2];
    const float* W_pool1 = (const float*)d_in[3];
    const float* b_pool1 = (const float*)d_in[4];
    const float* W_self1 = (const float*)d_in[5];
    const float* W_neigh1= (const float*)d_in[6];
    const float* b1      = (const float*)d_in[7];
    const float* W_pool2 = (const float*)d_in[8];
    const float* b_pool2 = (const float*)d_in[9];
    const float* W_self2 = (const float*)d_in[10];
    const float* W_neigh2= (const float*)d_in[11];
    const float* b2      = (const float*)d_in[12];

    const int M = in_sizes[0] / F;       // 50000
    const int E = in_sizes[1];           // 1600000

    __half *p, *agg, *h1, *x16, *w;
    int *cnt, *rowptr, *cursor, *eidx, *blksum;
    cudaGetSymbolAddress((void**)&p,      g_p);
    cudaGetSymbolAddress((void**)&agg,    g_agg);
    cudaGetSymbolAddress((void**)&h1,     g_h1);
    cudaGetSymbolAddress((void**)&x16,    g_x16);
    cudaGetSymbolAddress((void**)&w,      g_w);
    cudaGetSymbolAddress((void**)&cnt,    g_cnt);
    cudaGetSymbolAddress((void**)&rowptr, g_rowptr);
    cudaGetSymbolAddress((void**)&cursor, g_cursor);
    cudaGetSymbolAddress((void**)&eidx,   g_eidx);
    cudaGetSymbolAddress((void**)&blksum, g_blksum);
    float* out = (float*)d_out;

    const __half* rWp1 = w + 0 * F * F;
    const __half* rWs1 = w + 1 * F * F;
    const __half* rWn1 = w + 2 * F * F;
    const __half* rWp2 = w + 3 * F * F;
    const __half* rWs2 = w + 4 * F * F;
    const __half* rWn2 = w + 5 * F * F;

    cudaFuncSetAttribute(gemm_tc_kernel<false, false, true>,
                         cudaFuncAttributeMaxDynamicSharedMemorySize, SMEM_BYTES);
    cudaFuncSetAttribute(gemm_tc_kernel<true, true, true>,
                         cudaFuncAttributeMaxDynamicSharedMemorySize, SMEM_BYTES);
    cudaFuncSetAttribute(gemm_tc_kernel<true, true, false>,
                         cudaFuncAttributeMaxDynamicSharedMemorySize, SMEM_BYTES);

    // Row chunking: c0 = [0, MC0), c1 = [MC0, M). MC0 multiple of 64.
    const int MC0 = ((M / 2) + 63) & ~63;       // 25024
    const int MC1 = M - MC0;                    // 24976
    const int gb0 = (MC0 + 63) / 64;
    const int gb1 = (MC1 + 63) / 64;
    const int gblocks = (M + 63) / 64;
    const int eblocks = (E + 255) / 256;
    const int nb      = (M + SCAN_CHUNK - 1) / SCAN_CHUNK;
    const int wb0 = (MC0 * 32 + 255) / 256;
    const int wb1 = (MC1 * 32 + 255) / 256;

    // --- side streams + events (host objects only; created once) ---
    static cudaStream_t s_csr = nullptr, s_b = nullptr;
    static cudaEvent_t ev_fork = nullptr, ev_csr = nullptr,
                       ev_g0a = nullptr, ev_g1a = nullptr,
                       ev_g0b = nullptr, ev_g1b = nullptr;
    if (s_csr == nullptr) {
        cudaStreamCreateWithFlags(&s_csr, cudaStreamNonBlocking);
        cudaStreamCreateWithFlags(&s_b, cudaStreamNonBlocking);
        cudaEventCreateWithFlags(&ev_fork, cudaEventDisableTiming);
        cudaEventCreateWithFlags(&ev_csr, cudaEventDisableTiming);
        cudaEventCreateWithFlags(&ev_g0a, cudaEventDisableTiming);
        cudaEventCreateWithFlags(&ev_g1a, cudaEventDisableTiming);
        cudaEventCreateWithFlags(&ev_g0b, cudaEventDisableTiming);
        cudaEventCreateWithFlags(&ev_g1b, cudaEventDisableTiming);
    }

    // Fork CSR branch (first two CSR kernels overlap conv + pool1)
    cudaEventRecord(ev_fork, 0);
    cudaStreamWaitEvent(s_csr, ev_fork, 0);
    cudaMemsetAsync(cnt, 0, (size_t)M * sizeof(int), s_csr);        // 1
    hist_kernel<<<eblocks, 256, 0, s_csr>>>(dst, cnt, E);           // 2

    // Main: convert inputs + pool GEMM layer 1
    conv_w_kernel<<<dim3(8, 6), 256>>>(W_pool1, W_self1, W_neigh1,
                                       W_pool2, W_self2, W_neigh2, w);   // 3
    conv_x_kernel<<<(M * F / 8 + 255) / 256, 256>>>(x, x16, M * F / 8);  // 4
    gemm_tc_kernel<false, false, true><<<gblocks, 256, SMEM_BYTES>>>(    // 5: pool GEMM L1
        x16, rWp1, nullptr, nullptr, b_pool1, p, M);

    // CSR branch continues
    scan_block_kernel<<<nb, SCAN_CHUNK, 0, s_csr>>>(cnt, rowptr, blksum, M);
    scan_partials_kernel<<<1, 32, 0, s_csr>>>(blksum, nb);
    add_offsets_kernel<<<(M + 256) / 256, 256, 0, s_csr>>>(rowptr, cursor, blksum, M, E);
    fill_csr_kernel<<<eblocks, 256, 0, s_csr>>>(src, dst, cursor, eidx, E);
    cudaEventRecord(ev_csr, s_csr);

    // ---- Layer 1: chunked gather + fused, pipelined ----
    cudaStreamWaitEvent(0, ev_csr, 0);
    gather_max_kernel<<<wb0, 256>>>((const __half2*)p, rowptr, eidx,
                                    (__half2*)agg, 0, MC0);
    cudaEventRecord(ev_g0a, 0);
    cudaStreamWaitEvent(s_b, ev_g0a, 0);
    gather_max_kernel<<<wb1, 256, 0, s_b>>>((const __half2*)p, rowptr, eidx,
                                            (__half2*)agg, MC0, M);
    cudaEventRecord(ev_g1a, s_b);
    // fused chunk 0 overlaps gather chunk 1
    gemm_tc_kernel<true, true, true><<<gb0, 256, SMEM_BYTES>>>(
        x16, rWs1, agg, rWn1, b1, h1, MC0);
    cudaStreamWaitEvent(0, ev_g1a, 0);
    gemm_tc_kernel<true, true, true><<<gb1, 256, SMEM_BYTES>>>(
        x16 + (size_t)MC0 * F, rWs1, agg + (size_t)MC0 * F, rWn1, b1,
        h1 + (size_t)MC0 * F, MC1);

    // ---- Layer 2 ----
    gemm_tc_kernel<false, false, true><<<gblocks, 256, SMEM_BYTES>>>(
        h1, rWp2, nullptr, nullptr, b_pool2, p, M);
    gather_max_kernel<<<wb0, 256>>>((const __half2*)p, rowptr, eidx,
                                    (__half2*)agg, 0, MC0);
    cudaEventRecord(ev_g0b, 0);
    cudaStreamWaitEvent(s_b, ev_g0b, 0);
    gather_max_kernel<<<wb1, 256, 0, s_b>>>((const __half2*)p, rowptr, eidx,
                                            (__half2*)agg, MC0, M);
    cudaEventRecord(ev_g1b, s_b);
    gemm_tc_kernel<true, true, false><<<gb0, 256, SMEM_BYTES>>>(
        h1, rWs2, agg, rWn2, b2, out, MC0);
    cudaStreamWaitEvent(0, ev_g1b, 0);
    gemm_tc_kernel<true, true, false><<<gb1, 256, SMEM_BYTES>>>(
        h1 + (size_t)MC0 * F, rWs2, agg + (size_t)MC0 * F, rWn2, b2,
        out + (size_t)MC0 * F, MC1);
}

// round 10
// speedup vs baseline: 1.0733x; 1.0644x over previous
#include <cuda_runtime.h>
#include <cuda_fp16.h>
#include <cstdint>

// Problem constants (from reference setup_inputs)
#define NMAX 50048
#define EMAX 1600000
#define F 128

// Scratch (allocation-free rule: __device__ globals)
__device__ __align__(16) __half g_p[NMAX * F];    // relu(h @ W_pool + b_pool)
__device__ __align__(16) __half g_agg[NMAX * F];  // segment max
__device__ __align__(16) __half g_h1[NMAX * F];   // layer-1 output
__device__ __align__(16) __half g_x16[NMAX * F];  // fp16 copy of x
__device__ __align__(16) __half g_w[6 * F * F];   // fp16 weights

// CSR-by-dst scratch
__device__ int g_cnt[NMAX];
__device__ int g_rowptr[NMAX + 1];
__device__ int g_cursor[NMAX];
__device__ int g_eidx[EMAX];
__device__ int g_blksum[64];

// ---------------------------------------------------------------------------
// Helpers
// ---------------------------------------------------------------------------
__device__ __forceinline__ void cp16(void* smem_dst, const void* gsrc) {
    unsigned d = (unsigned)__cvta_generic_to_shared(smem_dst);
    asm volatile("cp.async.cg.shared.global [%0], [%1], 16;" :: "r"(d), "l"(gsrc));
}
#define CP_COMMIT() asm volatile("cp.async.commit_group;")
#define CP_WAIT0()  asm volatile("cp.async.wait_group 0;")

__device__ __forceinline__ void mma_f16(float* d, const unsigned* a, const unsigned* b) {
    asm volatile(
        "mma.sync.aligned.m16n8k16.row.col.f32.f16.f16.f32 "
        "{%0,%1,%2,%3}, {%4,%5,%6,%7}, {%8,%9}, {%0,%1,%2,%3};"
        : "+f"(d[0]), "+f"(d[1]), "+f"(d[2]), "+f"(d[3])
        : "r"(a[0]), "r"(a[1]), "r"(a[2]), "r"(a[3]), "r"(b[0]), "r"(b[1]));
}

__device__ __forceinline__ void ldsm_x4(unsigned* a, unsigned saddr) {
    asm volatile("ldmatrix.sync.aligned.m8n8.x4.shared.b16 {%0,%1,%2,%3}, [%4];"
        : "=r"(a[0]), "=r"(a[1]), "=r"(a[2]), "=r"(a[3]) : "r"(saddr));
}
__device__ __forceinline__ void ldsm_x2_trans(unsigned* b, unsigned saddr) {
    asm volatile("ldmatrix.sync.aligned.m8n8.x2.trans.shared.b16 {%0,%1}, [%2];"
        : "=r"(b[0]), "=r"(b[1]) : "r"(saddr));
}

// ---------------------------------------------------------------------------
// Prep kernels: convert x and the 6 weight matrices to fp16 (once per launch)
// ---------------------------------------------------------------------------
__global__ void conv_x_kernel(const float* __restrict__ in, __half* __restrict__ out, int n8)
{
    int i = blockIdx.x * blockDim.x + threadIdx.x;
    if (i < n8) {
        float4 v0 = ((const float4*)in)[i * 2];
        float4 v1 = ((const float4*)in)[i * 2 + 1];
        __half2 h[4];
        h[0] = __floats2half2_rn(v0.x, v0.y);
        h[1] = __floats2half2_rn(v0.z, v0.w);
        h[2] = __floats2half2_rn(v1.x, v1.y);
        h[3] = __floats2half2_rn(v1.z, v1.w);
        ((float4*)out)[i] = *(float4*)h;
    }
}

__global__ void conv_w_kernel(const float* w0, const float* w1, const float* w2,
                              const float* w3, const float* w4, const float* w5,
                              __half* __restrict__ out)
{
    const float* ws[6] = {w0, w1, w2, w3, w4, w5};
    const float* in = ws[blockIdx.y];
    __half* o = out + blockIdx.y * (F * F);
    int i = blockIdx.x * blockDim.x + threadIdx.x;
    float4 v0 = ((const float4*)in)[i * 2];
    float4 v1 = ((const float4*)in)[i * 2 + 1];
    __half2 h[4];
    h[0] = __floats2half2_rn(v0.x, v0.y);
    h[1] = __floats2half2_rn(v0.z, v0.w);
    h[2] = __floats2half2_rn(v1.x, v1.y);
    h[3] = __floats2half2_rn(v1.z, v1.w);
    ((float4*)o)[i] = *(float4*)h;
}

// ---------------------------------------------------------------------------
// FP16 tensor-core GEMM:  C[M,128] = epi( A1 @ W1 (+ A2 @ W2) + bias )
// Block: 256 thr = 8 warps (2x4), BM=64, BN=128, BK=64, cp.async dbl-buffered.
// POOL2: after the epilogue, compute P2 = relu(C_h1 @ Wp2 + bias2) from the
// smem-resident h1 tile (fused second GEMM; saves a kernel + h1 re-read).
// ---------------------------------------------------------------------------
#define SAH 72
#define SBH 136
#define AS_ELEM (64 * SAH)
#define BS_ELEM (64 * SBH)
#define AS_BYTES (AS_ELEM * 2)
#define BS_BYTES (BS_ELEM * 2)
#define SMEM_BYTES (2 * AS_BYTES + 2 * BS_BYTES)
// h1 tile (POOL2): 64 rows x 128 cols fp16 @ stride 136 halfs = 17408 B,
// lives in the (freed) 2xAS region [0, 18432). rowsq lives after it.
#define H1_STRIDE 136
#define ROWSQ_OFF 17408

template<bool TWO>
__device__ __forceinline__ void prefetch_tile(
    __half* As, __half* Bs,
    const __half* A1, const __half* W1, const __half* A2, const __half* W2,
    int t, int m0, int M, int tid)
{
    int buf = t & 1;
    const __half* A = (TWO && t >= 2) ? A2 : A1;
    const __half* W = (TWO && t >= 2) ? W2 : W1;
    int kk = (t & 1) * 64;
#pragma unroll
    for (int i = 0; i < 2; i++) {
        int c  = tid + i * 256;
        int r  = c >> 3;
        int c8 = (c & 7) * 8;
        int m  = m0 + r;
        if (m < M)
            cp16(&As[buf * AS_ELEM + r * SAH + c8], A + (size_t)m * F + kk + c8);
    }
#pragma unroll
    for (int i = 0; i < 4; i++) {
        int c  = tid + i * 256;
        int r  = c >> 4;
        int n8 = (c & 15) * 8;
        cp16(&Bs[buf * BS_ELEM + r * SBH + n8], W + (size_t)(kk + r) * F + n8);
    }
    CP_COMMIT();
}

template<bool TWO, bool L2N, bool HALFOUT, bool POOL2>
__global__ __launch_bounds__(256, 3)
void gemm_tc_kernel(const __half* __restrict__ A1, const __half* __restrict__ W1,
                    const __half* __restrict__ A2, const __half* __restrict__ W2,
                    const float* __restrict__ bias, void* __restrict__ Cout,
                    const __half* __restrict__ Wp2, const float* __restrict__ bias2,
                    __half* __restrict__ Pout, int M)
{
    extern __shared__ __align__(16) char smc[];
    __half* As = (__half*)smc;
    __half* Bs = (__half*)(smc + 2 * AS_BYTES);

    const int tid  = threadIdx.x;
    const int wid  = tid >> 5;
    const int lane = tid & 31;
    const int wr   = wid >> 2;
    const int wc   = wid & 3;
    const int g    = lane >> 2;
    const int tig  = lane & 3;
    const int m0   = blockIdx.x * 64;

    unsigned as_u32 = (unsigned)__cvta_generic_to_shared(As);
    unsigned bs_u32 = (unsigned)__cvta_generic_to_shared(Bs);
    const int lrow = lane & 15;
    const int kadd = (lane & 16) ? 8 : 0;
    unsigned aaddr[2];
#pragma unroll
    for (int mf = 0; mf < 2; mf++)
        aaddr[mf] = as_u32 + ((wr * 32 + mf * 16 + lrow) * SAH + kadd) * 2;
    unsigned baddr[4];
#pragma unroll
    for (int nf = 0; nf < 4; nf++)
        baddr[nf] = bs_u32 + (lrow * SBH + (wc * 32 + nf * 8)) * 2;

    float acc[2][4][4];
#pragma unroll
    for (int mf = 0; mf < 2; mf++)
#pragma unroll
        for (int nf = 0; nf < 4; nf++)
#pragma unroll
            for (int q = 0; q < 4; q++) acc[mf][nf][q] = 0.0f;

    const int T = TWO ? 4 : 2;
    prefetch_tile<TWO>(As, Bs, A1, W1, A2, W2, 0, m0, M, tid);

    for (int t = 0; t < T; t++) {
        CP_WAIT0();
        __syncthreads();
        if (t + 1 < T)
            prefetch_tile<TWO>(As, Bs, A1, W1, A2, W2, t + 1, m0, M, tid);

        const unsigned abase = (t & 1) * AS_BYTES;
        const unsigned bbase = (t & 1) * BS_BYTES;

#pragma unroll
        for (int s = 0; s < 4; s++) {
            unsigned a[2][4], b[4][2];
#pragma unroll
            for (int mf = 0; mf < 2; mf++)
                ldsm_x4(a[mf], aaddr[mf] + abase + s * 32);
#pragma unroll
            for (int nf = 0; nf < 4; nf++)
                ldsm_x2_trans(b[nf], baddr[nf] + bbase + s * (16 * SBH * 2));
#pragma unroll
            for (int mf = 0; mf < 2; mf++)
#pragma unroll
                for (int nf = 0; nf < 4; nf++)
                    mma_f16(acc[mf][nf], a[mf], b[nf]);
        }
    }

    // ---- epilogue ----
    __syncthreads();           // all smem reads from the main loop are done

    if (POOL2) {
        // prefetch full Wp2 (128x128 fp16) into both Bs buffers now,
        // hiding the load behind the epilogue arithmetic.
#pragma unroll
        for (int i = 0; i < 8; i++) {
            int c   = tid + i * 256;        // 2048 16B-chunks
            int buf = c >> 10;              // 0..1 (k-half)
            int cc  = c & 1023;
            int r   = cc >> 4;
            int n8  = (cc & 15) * 8;
            cp16(&Bs[buf * BS_ELEM + r * SBH + n8],
                 Wp2 + (size_t)(buf * 64 + r) * F + n8);
        }
        CP_COMMIT();
    }

    float bv0[4], bv1[4];
#pragma unroll
    for (int nf = 0; nf < 4; nf++) {
        int cb = wc * 32 + nf * 8 + 2 * tig;
        bv0[nf] = bias[cb];
        bv1[nf] = bias[cb + 1];
    }
#pragma unroll
    for (int mf = 0; mf < 2; mf++)
#pragma unroll
        for (int nf = 0; nf < 4; nf++) {
            acc[mf][nf][0] += bv0[nf];
            acc[mf][nf][1] += bv1[nf];
            acc[mf][nf][2] += bv0[nf];
            acc[mf][nf][3] += bv1[nf];
        }

    float inv[2][2];
#pragma unroll
    for (int mf = 0; mf < 2; mf++) { inv[mf][0] = 1.f; inv[mf][1] = 1.f; }

    if (L2N) {
        float* rowsq = (float*)(smc + ROWSQ_OFF);
        if (tid < 64) rowsq[tid] = 0.0f;
        __syncthreads();
#pragma unroll
        for (int mf = 0; mf < 2; mf++) {
#pragma unroll
            for (int half = 0; half < 2; half++) {
                float s = 0.f;
#pragma unroll
                for (int nf = 0; nf < 4; nf++) {
                    float v0 = acc[mf][nf][half * 2 + 0];
                    float v1 = acc[mf][nf][half * 2 + 1];
                    s = fmaf(v0, v0, fmaf(v1, v1, s));
                }
                s += __shfl_xor_sync(0xffffffffu, s, 1);
                s += __shfl_xor_sync(0xffffffffu, s, 2);
                if (tig == 0) {
                    int r = wr * 32 + mf * 16 + half * 8 + g;
                    atomicAdd(&rowsq[r], s);
                }
            }
        }
        __syncthreads();
#pragma unroll
        for (int mf = 0; mf < 2; mf++)
#pragma unroll
            for (int half = 0; half < 2; half++) {
                int r = wr * 32 + mf * 16 + half * 8 + g;
                inv[mf][half] = 1.0f / fmaxf(sqrtf(rowsq[r]), 1e-12f);
            }
    }

    // store (relu; fp16/fp32) and, for POOL2, mirror the h1 tile into smem
#pragma unroll
    for (int mf = 0; mf < 2; mf++) {
#pragma unroll
        for (int half = 0; half < 2; half++) {
            int mloc = wr * 32 + mf * 16 + half * 8 + g;
            int m = m0 + mloc;
            float s = inv[mf][half];
#pragma unroll
            for (int nf = 0; nf < 4; nf++) {
                float v0 = fmaxf(acc[mf][nf][half * 2 + 0] * s, 0.f);
                float v1 = fmaxf(acc[mf][nf][half * 2 + 1] * s, 0.f);
                int col = wc * 32 + nf * 8 + 2 * tig;
                if (HALFOUT) {
                    __half2 hv = __floats2half2_rn(v0, v1);
                    if (m < M)
                        *(__half2*)((__half*)Cout + (size_t)m * F + col) = hv;
                    if (POOL2)
                        *(__half2*)(smc + (mloc * H1_STRIDE + col) * 2) = hv;
                } else {
                    if (m < M)
                        *(float2*)((float*)Cout + (size_t)m * F + col) = make_float2(v0, v1);
                }
            }
        }
    }

    if (POOL2) {
        CP_WAIT0();
        __syncthreads();       // h1 tile + Wp2 tiles visible to all

        unsigned a2addr[2];
#pragma unroll
        for (int mf = 0; mf < 2; mf++)
            a2addr[mf] = as_u32 + ((wr * 32 + mf * 16 + lrow) * H1_STRIDE + kadd) * 2;

        float acc2[2][4][4];
#pragma unroll
        for (int mf = 0; mf < 2; mf++)
#pragma unroll
            for (int nf = 0; nf < 4; nf++)
#pragma unroll
                for (int q = 0; q < 4; q++) acc2[mf][nf][q] = 0.0f;

#pragma unroll
        for (int t = 0; t < 2; t++) {
#pragma unroll
            for (int s = 0; s < 4; s++) {
                unsigned a[2][4], b[4][2];
#pragma unroll
                for (int mf = 0; mf < 2; mf++)
                    ldsm_x4(a[mf], a2addr[mf] + (t * 64 + s * 16) * 2);
#pragma unroll
                for (int nf = 0; nf < 4; nf++)
                    ldsm_x2_trans(b[nf], baddr[nf] + t * BS_BYTES + s * (16 * SBH * 2));
#pragma unroll
                for (int mf = 0; mf < 2; mf++)
#pragma unroll
                    for (int nf = 0; nf < 4; nf++)
                        mma_f16(acc2[mf][nf], a[mf], b[nf]);
            }
        }

        float pb0[4], pb1[4];
#pragma unroll
        for (int nf = 0; nf < 4; nf++) {
            int cb = wc * 32 + nf * 8 + 2 * tig;
            pb0[nf] = bias2[cb];
            pb1[nf] = bias2[cb + 1];
        }
#pragma unroll
        for (int mf = 0; mf < 2; mf++) {
#pragma unroll
            for (int half = 0; half < 2; half++) {
                int m = m0 + wr * 32 + mf * 16 + half * 8 + g;
                if (m >= M) continue;
#pragma unroll
                for (int nf = 0; nf < 4; nf++) {
                    float v0 = fmaxf(acc2[mf][nf][half * 2 + 0] + pb0[nf], 0.f);
                    float v1 = fmaxf(acc2[mf][nf][half * 2 + 1] + pb1[nf], 0.f);
                    int col = wc * 32 + nf * 8 + 2 * tig;
                    __half2 hv = __floats2half2_rn(v0, v1);
                    *(__half2*)(Pout + (size_t)m * F + col) = hv;
                }
            }
        }
    }
}

// ---------------------------------------------------------------------------
// CSR-by-dst build
// ---------------------------------------------------------------------------
__global__ void hist_kernel(const int* __restrict__ dst, int* __restrict__ cnt, int E)
{
    int e = blockIdx.x * blockDim.x + threadIdx.x;
    if (e < E) atomicAdd(&cnt[dst[e]], 1);
}

#define SCAN_CHUNK 1024
__global__ void scan_block_kernel(const int* __restrict__ cnt, int* __restrict__ rowptr,
                                  int* __restrict__ blksum, int N)
{
    __shared__ int s[SCAN_CHUNK];
    int i = blockIdx.x * SCAN_CHUNK + threadIdx.x;
    int v = (i < N) ? cnt[i] : 0;
    s[threadIdx.x] = v;
    __syncthreads();
#pragma unroll
    for (int off = 1; off < SCAN_CHUNK; off <<= 1) {
        int t = (threadIdx.x >= off) ? s[threadIdx.x - off] : 0;
        __syncthreads();
        s[threadIdx.x] += t;
        __syncthreads();
    }
    if (i < N) rowptr[i] = s[threadIdx.x] - v;
    if (threadIdx.x == SCAN_CHUNK - 1) blksum[blockIdx.x] = s[threadIdx.x];
}

__global__ void scan_partials_kernel(int* blksum, int nb)
{
    int lane = threadIdx.x & 31;
    int v0 = (lane < nb) ? blksum[lane] : 0;
    int v1 = (lane + 32 < nb) ? blksum[lane + 32] : 0;
    int s0 = v0, s1 = v1;
#pragma unroll
    for (int o = 1; o < 32; o <<= 1) {
        int t0 = __shfl_up_sync(0xffffffffu, s0, o);
        int t1 = __shfl_up_sync(0xffffffffu, s1, o);
        if (lane >= o) { s0 += t0; s1 += t1; }
    }
    int tot0 = __shfl_sync(0xffffffffu, s0, 31);
    s1 += tot0;
    if (lane < nb) blksum[lane] = s0 - v0;
    if (lane + 32 < nb) blksum[lane + 32] = s1 - v1;
}

__global__ void add_offsets_kernel(int* __restrict__ rowptr, int* __restrict__ cursor,
                                   const int* __restrict__ blksum, int N, int E)
{
    int i = blockIdx.x * blockDim.x + threadIdx.x;
    if (i < N) {
        int v = rowptr[i] + blksum[i >> 10];
        rowptr[i] = v;
        cursor[i] = v;
    }
    if (i == N) rowptr[N] = E;
}

__global__ void fill_csr_kernel(const int* __restrict__ src, const int* __restrict__ dst,
                                int* __restrict__ cursor, int* __restrict__ eidx, int E)
{
    int e = blockIdx.x * blockDim.x + threadIdx.x;
    if (e < E) {
        int pos = atomicAdd(&cursor[dst[e]], 1);
        eidx[pos] = src[e];
    }
}

// ---------------------------------------------------------------------------
// Gather-max over fp16 rows: one warp per dst node, lane owns 4 halfs (8B)
// ---------------------------------------------------------------------------
__global__ void gather_max_kernel(const __half2* __restrict__ p2,
                                  const int* __restrict__ rowptr,
                                  const int* __restrict__ eidx,
                                  __half2* __restrict__ agg, int N)
{
    int warp = (blockIdx.x * blockDim.x + threadIdx.x) >> 5;
    int lane = threadIdx.x & 31;
    if (warp >= N) return;
    int beg = __ldg(&rowptr[warp]);
    int end = __ldg(&rowptr[warp + 1]);

    __half2 z = __float2half2_rn(0.f);
    __half2 a0 = z, a1 = z;
    int i = beg;
    for (; i + 3 < end; i += 4) {
        int s0 = __ldg(&eidx[i]);
        int s1 = __ldg(&eidx[i + 1]);
        int s2 = __ldg(&eidx[i + 2]);
        int s3 = __ldg(&eidx[i + 3]);
        const __half2* r0 = p2 + (size_t)s0 * 64 + lane * 2;
        const __half2* r1 = p2 + (size_t)s1 * 64 + lane * 2;
        const __half2* r2 = p2 + (size_t)s2 * 64 + lane * 2;
        const __half2* r3 = p2 + (size_t)s3 * 64 + lane * 2;
        __half2 v00 = r0[0], v01 = r0[1];
        __half2 v10 = r1[0], v11 = r1[1];
        __half2 v20 = r2[0], v21 = r2[1];
        __half2 v30 = r3[0], v31 = r3[1];
        a0 = __hmax2(a0, __hmax2(__hmax2(v00, v10), __hmax2(v20, v30)));
        a1 = __hmax2(a1, __hmax2(__hmax2(v01, v11), __hmax2(v21, v31)));
    }
    for (; i < end; i++) {
        int s = __ldg(&eidx[i]);
        const __half2* r = p2 + (size_t)s * 64 + lane * 2;
        a0 = __hmax2(a0, r[0]);
        a1 = __hmax2(a1, r[1]);
    }
    __half2 o[2] = {a0, a1};
    *(float2*)(agg + (size_t)warp * 64 + lane * 2) = *(float2*)o;
}

// ---------------------------------------------------------------------------
extern "C" void kernel_launch(void* const* d_in, const int* in_sizes, int n_in,
                              void* d_out, int out_size)
{
    const float* x       = (const float*)d_in[0];
    const int*   src     = (const int*)  d_in[1];
    const int*   dst     = (const int*)  d_in[2];
    const float* W_pool1 = (const float*)d_in[3];
    const float* b_pool1 = (const float*)d_in[4];
    const float* W_self1 = (const float*)d_in[5];
    const float* W_neigh1= (const float*)d_in[6];
    const float* b1      = (const float*)d_in[7];
    const float* W_pool2 = (const float*)d_in[8];
    const float* b_pool2 = (const float*)d_in[9];
    const float* W_self2 = (const float*)d_in[10];
    const float* W_neigh2= (const float*)d_in[11];
    const float* b2      = (const float*)d_in[12];

    const int M = in_sizes[0] / F;       // 50000
    const int E = in_sizes[1];           // 1600000

    __half *p, *agg, *h1, *x16, *w;
    int *cnt, *rowptr, *cursor, *eidx, *blksum;
    cudaGetSymbolAddress((void**)&p,      g_p);
    cudaGetSymbolAddress((void**)&agg,    g_agg);
    cudaGetSymbolAddress((void**)&h1,     g_h1);
    cudaGetSymbolAddress((void**)&x16,    g_x16);
    cudaGetSymbolAddress((void**)&w,      g_w);
    cudaGetSymbolAddress((void**)&cnt,    g_cnt);
    cudaGetSymbolAddress((void**)&rowptr, g_rowptr);
    cudaGetSymbolAddress((void**)&cursor, g_cursor);
    cudaGetSymbolAddress((void**)&eidx,   g_eidx);
    cudaGetSymbolAddress((void**)&blksum, g_blksum);
    float* out = (float*)d_out;

    const __half* rWp1 = w + 0 * F * F;
    const __half* rWs1 = w + 1 * F * F;
    const __half* rWn1 = w + 2 * F * F;
    const __half* rWp2 = w + 3 * F * F;
    const __half* rWs2 = w + 4 * F * F;
    const __half* rWn2 = w + 5 * F * F;

    auto k_pool1  = gemm_tc_kernel<false, false, true,  false>;  // p1 = relu(x@Wp1+b)
    auto k_fused1 = gemm_tc_kernel<true,  true,  true,  true >;  // h1 + fused p2
    auto k_fused2 = gemm_tc_kernel<true,  true,  false, false>;  // out
    cudaFuncSetAttribute(k_pool1,  cudaFuncAttributeMaxDynamicSharedMemorySize, SMEM_BYTES);
    cudaFuncSetAttribute(k_fused1, cudaFuncAttributeMaxDynamicSharedMemorySize, SMEM_BYTES);
    cudaFuncSetAttribute(k_fused2, cudaFuncAttributeMaxDynamicSharedMemorySize, SMEM_BYTES);

    const int gblocks = (M + 63) / 64;
    const int eblocks = (E + 255) / 256;
    const int nb      = (M + SCAN_CHUNK - 1) / SCAN_CHUNK;
    const int wblocks = (M * 32 + 255) / 256;

    // --- side stream + events (host objects only; created once) ---
    static cudaStream_t s_csr = nullptr;
    static cudaEvent_t ev_fork = nullptr, ev_csr = nullptr;
    if (s_csr == nullptr) {
        cudaStreamCreateWithFlags(&s_csr, cudaStreamNonBlocking);
        cudaEventCreateWithFlags(&ev_fork, cudaEventDisableTiming);
        cudaEventCreateWithFlags(&ev_csr, cudaEventDisableTiming);
    }

    // Fork: CSR build overlaps conv + pool GEMM layer 1.
    cudaEventRecord(ev_fork, 0);
    cudaStreamWaitEvent(s_csr, ev_fork, 0);
    cudaMemsetAsync(cnt, 0, (size_t)M * sizeof(int), s_csr);        // 1
    hist_kernel<<<eblocks, 256, 0, s_csr>>>(dst, cnt, E);           // 2

    conv_w_kernel<<<dim3(8, 6), 256>>>(W_pool1, W_self1, W_neigh1,
                                       W_pool2, W_self2, W_neigh2, w);    // 3
    conv_x_kernel<<<(M * F / 8 + 255) / 256, 256>>>(x, x16, M * F / 8);   // 4
    k_pool1<<<gblocks, 256, SMEM_BYTES>>>(                                // 5 (ncu slot)
        x16, rWp1, nullptr, nullptr, b_pool1, p, nullptr, nullptr, nullptr, M);

    scan_block_kernel<<<nb, SCAN_CHUNK, 0, s_csr>>>(cnt, rowptr, blksum, M);
    scan_partials_kernel<<<1, 32, 0, s_csr>>>(blksum, nb);
    add_offsets_kernel<<<(M + 256) / 256, 256, 0, s_csr>>>(rowptr, cursor, blksum, M, E);
    fill_csr_kernel<<<eblocks, 256, 0, s_csr>>>(src, dst, cursor, eidx, E);
    cudaEventRecord(ev_csr, s_csr);

    // ---- Layer 1 (+fused pool2) ----
    cudaStreamWaitEvent(0, ev_csr, 0);
    gather_max_kernel<<<wblocks, 256>>>((const __half2*)p, rowptr, eidx, (__half2*)agg, M);
    k_fused1<<<gblocks, 256, SMEM_BYTES>>>(
        x16, rWs1, agg, rWn1, b1, h1, rWp2, b_pool2, p, M);

    // ---- Layer 2 ----
    gather_max_kernel<<<wblocks, 256>>>((const __half2*)p, rowptr, eidx, (__half2*)agg, M);
    k_fused2<<<gblocks, 256, SMEM_BYTES>>>(
        h1, rWs2, agg, rWn2, b2, out, nullptr, nullptr, nullptr, M);
}